// round 1
// baseline (speedup 1.0000x reference)
#include <cuda_runtime.h>
#include <cuda_bf16.h>
#include <float.h>

// ---------------------------------------------------------------------------
// StyleSwap:
//   content [4,256,64,64], style [256,64,64], PATCH=3, STRIDE=1
//   n = 62, npatches = 3844
// Decomposition:
//   G[b,r,s] = sum_c content[b,c,r] * style[c,s]   (r,s in [0,4096))
//   feat[b,(pi,pj),(qi,qj)] = sum_{dh,dw} G[b, (qi+dh)*64+qj+dw, (pi+dh)*64+pj+dw]
//                           = sum_{d in {0,1,2,64,65,66,128,129,130}} G[b, q+d, sp+d]
//   idx = argmax_p (feat + enc_bias[p])
//   dec[b,c,h,w] = sum_{(i,j) covering (h,w)} style[c, (pi+h-i)*64 + (pj+w-j)] + dec_bias[c]
//   intra[b,c,h,w] = cnt(h)*cnt(w) + intra_bias[c]       (data independent!)
//   out = dec / intra
// ---------------------------------------------------------------------------

#define B_ 4
#define C_ 256
#define HW_ 4096
#define NQ_ 62
#define NP_ 3844

// Scratch: G [4][4096][4096] fp32 = 268 MB, idx [4][62][62]
__device__ float g_G[(size_t)B_ * HW_ * HW_];
__device__ int   g_idx[B_ * NQ_ * NQ_];

// ---------------------------------------------------------------------------
// Kernel 1: batched SGEMM  G[b] = content_b^T (4096x256) @ style (256x4096)
// A[r,c] = content[b*C*HW + c*HW + r]  (contiguous in r -> coalesced)
// B[s,c] = style[c*HW + s]             (contiguous in s -> coalesced)
// 128x128x16 block tile, 256 threads, 8x8 per thread.
// ---------------------------------------------------------------------------
#define BM 128
#define BN 128
#define BK 16
#define TM 8
#define TN 8

__global__ __launch_bounds__(256) void gemm_kernel(
    const float* __restrict__ content, const float* __restrict__ style)
{
    __shared__ float As[BK][BM];
    __shared__ float Bs[BK][BN];

    const int b = blockIdx.z;
    const float* A = content + (size_t)b * C_ * HW_;   // [c][r]
    float* Cout = g_G + (size_t)b * HW_ * HW_;         // [r][s]

    const int row0 = blockIdx.y * BM;
    const int col0 = blockIdx.x * BN;
    const int tid = threadIdx.x;
    const int tr = (tid / 16) * TM;
    const int tc = (tid % 16) * TN;

    float acc[TM][TN];
#pragma unroll
    for (int m = 0; m < TM; m++)
#pragma unroll
        for (int n = 0; n < TN; n++) acc[m][n] = 0.0f;

    for (int k0 = 0; k0 < C_; k0 += BK) {
        // Load A tile: BK*BM = 2048 floats = 512 float4, 2 per thread
#pragma unroll
        for (int i = 0; i < 2; i++) {
            int idx = (tid + i * 256) * 4;
            int k = idx / BM, m = idx % BM;
            *(float4*)&As[k][m] =
                *(const float4*)&A[(size_t)(k0 + k) * HW_ + row0 + m];
            int k2 = idx / BN, n = idx % BN;
            *(float4*)&Bs[k2][n] =
                *(const float4*)&style[(size_t)(k0 + k2) * HW_ + col0 + n];
        }
        __syncthreads();

#pragma unroll
        for (int k = 0; k < BK; k++) {
            float a[TM], bv[TN];
            float4 a0 = *(float4*)&As[k][tr];
            float4 a1 = *(float4*)&As[k][tr + 4];
            a[0]=a0.x; a[1]=a0.y; a[2]=a0.z; a[3]=a0.w;
            a[4]=a1.x; a[5]=a1.y; a[6]=a1.z; a[7]=a1.w;
            float4 b0 = *(float4*)&Bs[k][tc];
            float4 b1 = *(float4*)&Bs[k][tc + 4];
            bv[0]=b0.x; bv[1]=b0.y; bv[2]=b0.z; bv[3]=b0.w;
            bv[4]=b1.x; bv[5]=b1.y; bv[6]=b1.z; bv[7]=b1.w;
#pragma unroll
            for (int m = 0; m < TM; m++)
#pragma unroll
                for (int n = 0; n < TN; n++)
                    acc[m][n] = fmaf(a[m], bv[n], acc[m][n]);
        }
        __syncthreads();
    }

#pragma unroll
    for (int m = 0; m < TM; m++) {
        size_t rbase = (size_t)(row0 + tr + m) * HW_ + col0 + tc;
#pragma unroll
        for (int n = 0; n < TN; n += 4) {
            float4 v = make_float4(acc[m][n], acc[m][n+1], acc[m][n+2], acc[m][n+3]);
            *(float4*)&Cout[rbase + n] = v;
        }
    }
}

// ---------------------------------------------------------------------------
// Kernel 2: feat aggregation (9 diagonal gathers from G) + argmax over p.
// One block per (b, qi); loops qj. Tie-break: lowest p (matches jnp.argmax).
// ---------------------------------------------------------------------------
__global__ __launch_bounds__(256) void argmax_kernel(const float* __restrict__ enc_bias)
{
    const int qi = blockIdx.x;
    const int b  = blockIdx.y;
    const float* Gb = g_G + (size_t)b * HW_ * HW_;

    __shared__ float s_bias[NP_];
    __shared__ float s_val[256];
    __shared__ int   s_idx[256];

    for (int i = threadIdx.x; i < NP_; i += 256) s_bias[i] = enc_bias[i];
    __syncthreads();

    for (int qj = 0; qj < NQ_; qj++) {
        float best = -FLT_MAX;
        int bestp = 0;
        const float* g0 = Gb + (size_t)(qi * 64 + qj) * HW_;

        for (int p = threadIdx.x; p < NP_; p += 256) {
            int pi = p / NQ_, pj = p % NQ_;
            const float* gp = g0 + pi * 64 + pj;
            float f = s_bias[p];
            // offsets d*4097 for d in {0,1,2,64,65,66,128,129,130}
            f += gp[(size_t)0   * 4097];
            f += gp[(size_t)1   * 4097];
            f += gp[(size_t)2   * 4097];
            f += gp[(size_t)64  * 4097];
            f += gp[(size_t)65  * 4097];
            f += gp[(size_t)66  * 4097];
            f += gp[(size_t)128 * 4097];
            f += gp[(size_t)129 * 4097];
            f += gp[(size_t)130 * 4097];
            if (f > best) { best = f; bestp = p; }
        }
        s_val[threadIdx.x] = best;
        s_idx[threadIdx.x] = bestp;
        __syncthreads();

        for (int s = 128; s > 0; s >>= 1) {
            if (threadIdx.x < s) {
                float v2 = s_val[threadIdx.x + s];
                int   i2 = s_idx[threadIdx.x + s];
                float v1 = s_val[threadIdx.x];
                int   i1 = s_idx[threadIdx.x];
                if (v2 > v1 || (v2 == v1 && i2 < i1)) {
                    s_val[threadIdx.x] = v2;
                    s_idx[threadIdx.x] = i2;
                }
            }
            __syncthreads();
        }
        if (threadIdx.x == 0)
            g_idx[(b * NQ_ + qi) * NQ_ + qj] = s_idx[0];
        __syncthreads();
    }
}

// ---------------------------------------------------------------------------
// Kernel 3: reconstruction.  One block per (b, h); threads = (c_group, w).
// out[b,c,h,w] = (dec_bias[c] + sum_{covering (i,j)} style[c, off(i,j)])
//               / (cnt(h)*cnt(w) + intra_bias[c])
// ---------------------------------------------------------------------------
__global__ __launch_bounds__(256) void output_kernel(
    const float* __restrict__ style,
    const float* __restrict__ dec_bias,
    const float* __restrict__ intra_bias,
    float* __restrict__ out)
{
    const int h = blockIdx.x;
    const int b = blockIdx.y;

    __shared__ int s_rows[3][NQ_];
    const int ilo = max(h - 2, 0), ihi = min(h, NQ_ - 1);
    const int cnth = ihi - ilo + 1;
    for (int t = threadIdx.x; t < cnth * NQ_; t += 256) {
        int r = t / NQ_, j = t % NQ_;
        s_rows[r][j] = g_idx[(b * NQ_ + ilo + r) * NQ_ + j];
    }
    __syncthreads();

    const int w = threadIdx.x % 64;
    const int jlo = max(w - 2, 0), jhi = min(w, NQ_ - 1);
    const int cntw = jhi - jlo + 1;
    const float cnt = (float)(cnth * cntw);

    // Precompute the (<=9) style offsets for this (h,w) once.
    int offs[9];
    int noff = 0;
    for (int i = ilo; i <= ihi; i++) {
        int kh = h - i;
        for (int j = jlo; j <= jhi; j++) {
            int kw = w - j;
            int p = s_rows[i - ilo][j];
            int pi = p / NQ_, pj = p % NQ_;
            offs[noff++] = (pi + kh) * 64 + (pj + kw);
        }
    }

    for (int c = threadIdx.x / 64; c < C_; c += 4) {
        const float* st = style + (size_t)c * HW_;
        float acc = dec_bias[c];
#pragma unroll 9
        for (int t = 0; t < noff; t++) acc += st[offs[t]];
        float intra = cnt + intra_bias[c];
        out[(((size_t)b * C_ + c) * 64 + h) * 64 + w] = acc / intra;
    }
}

// ---------------------------------------------------------------------------
extern "C" void kernel_launch(void* const* d_in, const int* in_sizes, int n_in,
                              void* d_out, int out_size)
{
    const float* content    = (const float*)d_in[0];
    const float* style_img  = (const float*)d_in[1];
    const float* enc_bias   = (const float*)d_in[2];
    const float* dec_bias   = (const float*)d_in[3];
    const float* intra_bias = (const float*)d_in[4];
    float* out = (float*)d_out;

    dim3 ggrid(HW_ / BN, HW_ / BM, B_);
    gemm_kernel<<<ggrid, 256>>>(content, style_img);

    dim3 agrid(NQ_, B_);
    argmax_kernel<<<agrid, 256>>>(enc_bias);

    dim3 ogrid(64, B_);
    output_kernel<<<ogrid, 256>>>(style_img, dec_bias, intra_bias, out);
}

// round 2
// speedup vs baseline: 1.0406x; 1.0406x over previous
#include <cuda_runtime.h>
#include <cuda_bf16.h>
#include <float.h>

// ---------------------------------------------------------------------------
// StyleSwap:
//   content [4,256,64,64], style [256,64,64], PATCH=3, STRIDE=1
//   n = 62, npatches = 3844
// Decomposition:
//   G[b,r,s] = sum_c content[b,c,r] * style[c,s]   (r,s in [0,4096))
//   feat[b,q,p] = sum_{o in {0,1,2,64,65,66,128,129,130}} G[b, q+o, sp+o]
//     where q = qi*64+qj, sp = pi*64+pj
//   idx = argmax_p (feat + enc_bias[p])
//   dec[b,c,h,w] = sum_{(i,j) covering (h,w)} style[c, (pi+h-i)*64 + (pj+w-j)] + dec_bias[c]
//   intra[b,c,h,w] = cnt(h)*cnt(w) + intra_bias[c]   (data independent)
//   out = dec / intra
// ---------------------------------------------------------------------------

#define B_ 4
#define C_ 256
#define HW_ 4096
#define NQ_ 62
#define NP_ 3844

__device__ float g_G[(size_t)B_ * HW_ * HW_];
__device__ int   g_idx[B_ * NQ_ * NQ_];

// ---------------------------------------------------------------------------
// Kernel 1: batched SGEMM  G[b] = content_b^T (4096x256) @ style (256x4096)
// ---------------------------------------------------------------------------
#define BM 128
#define BN 128
#define BK 16
#define TM 8
#define TN 8

__global__ __launch_bounds__(256) void gemm_kernel(
    const float* __restrict__ content, const float* __restrict__ style)
{
    __shared__ float As[BK][BM];
    __shared__ float Bs[BK][BN];

    const int b = blockIdx.z;
    const float* A = content + (size_t)b * C_ * HW_;   // [c][r]
    float* Cout = g_G + (size_t)b * HW_ * HW_;         // [r][s]

    const int row0 = blockIdx.y * BM;
    const int col0 = blockIdx.x * BN;
    const int tid = threadIdx.x;
    const int tr = (tid / 16) * TM;
    const int tc = (tid % 16) * TN;

    float acc[TM][TN];
#pragma unroll
    for (int m = 0; m < TM; m++)
#pragma unroll
        for (int n = 0; n < TN; n++) acc[m][n] = 0.0f;

    for (int k0 = 0; k0 < C_; k0 += BK) {
#pragma unroll
        for (int i = 0; i < 2; i++) {
            int idx = (tid + i * 256) * 4;
            int k = idx / BM, m = idx % BM;
            *(float4*)&As[k][m] =
                *(const float4*)&A[(size_t)(k0 + k) * HW_ + row0 + m];
            int k2 = idx / BN, n = idx % BN;
            *(float4*)&Bs[k2][n] =
                *(const float4*)&style[(size_t)(k0 + k2) * HW_ + col0 + n];
        }
        __syncthreads();

#pragma unroll
        for (int k = 0; k < BK; k++) {
            float a[TM], bv[TN];
            float4 a0 = *(float4*)&As[k][tr];
            float4 a1 = *(float4*)&As[k][tr + 4];
            a[0]=a0.x; a[1]=a0.y; a[2]=a0.z; a[3]=a0.w;
            a[4]=a1.x; a[5]=a1.y; a[6]=a1.z; a[7]=a1.w;
            float4 b0 = *(float4*)&Bs[k][tc];
            float4 b1 = *(float4*)&Bs[k][tc + 4];
            bv[0]=b0.x; bv[1]=b0.y; bv[2]=b0.z; bv[3]=b0.w;
            bv[4]=b1.x; bv[5]=b1.y; bv[6]=b1.z; bv[7]=b1.w;
#pragma unroll
            for (int m = 0; m < TM; m++)
#pragma unroll
                for (int n = 0; n < TN; n++)
                    acc[m][n] = fmaf(a[m], bv[n], acc[m][n]);
        }
        __syncthreads();
    }

#pragma unroll
    for (int m = 0; m < TM; m++) {
        size_t rbase = (size_t)(row0 + tr + m) * HW_ + col0 + tc;
#pragma unroll
        for (int n = 0; n < TN; n += 4) {
            float4 v = make_float4(acc[m][n], acc[m][n+1], acc[m][n+2], acc[m][n+3]);
            *(float4*)&Cout[rbase + n] = v;
        }
    }
}

// ---------------------------------------------------------------------------
// Kernel 2: feat aggregation + argmax, shared-memory row-ring version.
// Block = (qi, qj-half, b). Stages the 9 needed G rows per qj step in a
// 3-band x 4-slot smem ring (rows full 4096 floats), prefetching 3 rows/step.
// Gather becomes conflict-free LDS; argmax via warp shuffle reduction.
// smem: ring 3*4*4096 floats (192KB) + bias 3844 floats (~15KB) = ~207KB.
// ---------------------------------------------------------------------------
#define QJ_PER_BLOCK 31
#define RING_FLOATS (3 * 4 * HW_)

extern __shared__ float s_dyn[];

__global__ __launch_bounds__(256, 1) void argmax_kernel(const float* __restrict__ enc_bias)
{
    const int qi   = blockIdx.x;
    const int qj0  = blockIdx.y * QJ_PER_BLOCK;
    const int b    = blockIdx.z;
    const int tid  = threadIdx.x;
    const int lane = tid & 31;
    const int wid  = tid >> 5;

    float* ring   = s_dyn;                 // [band 0..2][slot 0..3][4096]
    float* s_bias = s_dyn + RING_FLOATS;   // [3844]

    const float* Gb = g_G + (size_t)b * HW_ * HW_;

    __shared__ float s_rv[8];
    __shared__ int   s_ri[8];

    for (int i = tid; i < NP_; i += 256) s_bias[i] = enc_bias[i];

    // Preload rows r' = qj0 .. qj0+2 for all 3 bands.
    // Band k stages absolute row (qi+k)*64 + r' into slot (r' & 3).
#pragma unroll
    for (int r = 0; r < 3; r++) {
        int rp = qj0 + r;
#pragma unroll
        for (int k = 0; k < 3; k++) {
            const float4* src = (const float4*)(Gb + (((size_t)(qi + k) << 6) + rp) * HW_);
            float4* dst = (float4*)(ring + (k * 4 + (rp & 3)) * HW_);
            for (int i = tid; i < HW_ / 4; i += 256) dst[i] = src[i];
        }
    }
    __syncthreads();

    for (int qj = qj0; qj < qj0 + QJ_PER_BLOCK; qj++) {
        // Prefetch rows r' = qj+3 (slot (qj+3)&3 == (qj-1)&3, not read this step).
        {
            int rp = qj + 3;
            if (rp < 64) {
#pragma unroll
                for (int k = 0; k < 3; k++) {
                    const float4* src = (const float4*)(Gb + (((size_t)(qi + k) << 6) + rp) * HW_);
                    float4* dst = (float4*)(ring + (k * 4 + (rp & 3)) * HW_);
                    for (int i = tid; i < HW_ / 4; i += 256) dst[i] = src[i];
                }
            }
        }

        // 9 row pointers: band k, dw in {0,1,2}: row r' = qj+dw, col offset 64k+dw.
        const float* pr[3][3];
#pragma unroll
        for (int k = 0; k < 3; k++)
#pragma unroll
            for (int dw = 0; dw < 3; dw++)
                pr[k][dw] = ring + (k * 4 + ((qj + dw) & 3)) * HW_ + 64 * k + dw;

        float best = -FLT_MAX;
        int bestp = 0;

        for (int p = tid; p < NP_; p += 256) {
            int pi = p / NQ_;
            int sp = p + 2 * pi;          // pi*64 + pj
            float a0 = pr[0][0][sp];
            float a1 = pr[0][1][sp];
            float a2 = pr[0][2][sp];
            float a3 = pr[1][0][sp];
            float a4 = pr[1][1][sp];
            float a5 = pr[1][2][sp];
            float a6 = pr[2][0][sp];
            float a7 = pr[2][1][sp];
            float a8 = pr[2][2][sp];
            float s = (((a0 + a1) + (a2 + a3)) + ((a4 + a5) + (a6 + a7)))
                      + (a8 + s_bias[p]);
            if (s > best) { best = s; bestp = p; }
        }

        // Warp-level argmax (ties -> lowest p).
#pragma unroll
        for (int off = 16; off > 0; off >>= 1) {
            float v2 = __shfl_down_sync(0xFFFFFFFFu, best, off);
            int   i2 = __shfl_down_sync(0xFFFFFFFFu, bestp, off);
            if (v2 > best || (v2 == best && i2 < bestp)) { best = v2; bestp = i2; }
        }
        if (lane == 0) { s_rv[wid] = best; s_ri[wid] = bestp; }
        __syncthreads();

        if (tid == 0) {
            float bv = s_rv[0]; int bi = s_ri[0];
#pragma unroll
            for (int w = 1; w < 8; w++) {
                float v2 = s_rv[w]; int i2 = s_ri[w];
                if (v2 > bv || (v2 == bv && i2 < bi)) { bv = v2; bi = i2; }
            }
            g_idx[(b * NQ_ + qi) * NQ_ + qj] = bi;
        }
        __syncthreads();
    }
}

// ---------------------------------------------------------------------------
// Kernel 3: reconstruction.
// ---------------------------------------------------------------------------
__global__ __launch_bounds__(256) void output_kernel(
    const float* __restrict__ style,
    const float* __restrict__ dec_bias,
    const float* __restrict__ intra_bias,
    float* __restrict__ out)
{
    const int h = blockIdx.x;
    const int b = blockIdx.y;

    __shared__ int s_rows[3][NQ_];
    const int ilo = max(h - 2, 0), ihi = min(h, NQ_ - 1);
    const int cnth = ihi - ilo + 1;
    for (int t = threadIdx.x; t < cnth * NQ_; t += 256) {
        int r = t / NQ_, j = t % NQ_;
        s_rows[r][j] = g_idx[(b * NQ_ + ilo + r) * NQ_ + j];
    }
    __syncthreads();

    const int w = threadIdx.x % 64;
    const int jlo = max(w - 2, 0), jhi = min(w, NQ_ - 1);
    const int cntw = jhi - jlo + 1;
    const float cnt = (float)(cnth * cntw);

    int offs[9];
    int noff = 0;
    for (int i = ilo; i <= ihi; i++) {
        int kh = h - i;
        for (int j = jlo; j <= jhi; j++) {
            int kw = w - j;
            int p = s_rows[i - ilo][j];
            int pi = p / NQ_, pj = p % NQ_;
            offs[noff++] = (pi + kh) * 64 + (pj + kw);
        }
    }

    for (int c = threadIdx.x / 64; c < C_; c += 4) {
        const float* st = style + (size_t)c * HW_;
        float acc = dec_bias[c];
#pragma unroll 9
        for (int t = 0; t < noff; t++) acc += st[offs[t]];
        float intra = cnt + intra_bias[c];
        out[(((size_t)b * C_ + c) * 64 + h) * 64 + w] = acc / intra;
    }
}

// ---------------------------------------------------------------------------
extern "C" void kernel_launch(void* const* d_in, const int* in_sizes, int n_in,
                              void* d_out, int out_size)
{
    const float* content    = (const float*)d_in[0];
    const float* style_img  = (const float*)d_in[1];
    const float* enc_bias   = (const float*)d_in[2];
    const float* dec_bias   = (const float*)d_in[3];
    const float* intra_bias = (const float*)d_in[4];
    float* out = (float*)d_out;

    dim3 ggrid(HW_ / BN, HW_ / BM, B_);
    gemm_kernel<<<ggrid, 256>>>(content, style_img);

    static int smem_set = 0;
    const int smem_bytes = (RING_FLOATS + NP_) * sizeof(float);
    if (!smem_set) {
        cudaFuncSetAttribute(argmax_kernel,
                             cudaFuncAttributeMaxDynamicSharedMemorySize, smem_bytes);
        smem_set = 1;
    }
    dim3 agrid(NQ_, 2, B_);
    argmax_kernel<<<agrid, 256, smem_bytes>>>(enc_bias);

    dim3 ogrid(64, B_);
    output_kernel<<<ogrid, 256>>>(style_img, dec_bias, intra_bias, out);
}